// round 9
// baseline (speedup 1.0000x reference)
#include <cuda_runtime.h>
#include <cuda_fp16.h>
#include <cstdint>

// ---------------- Problem constants ----------------
#define B_TOTAL   8192
#define F_DIM     64
#define NX        82
#define NY        67
#define NYP       96            // prep W layout (unchanged)
#define NU        72            // used N (ceil(67/8)*8)
#define P_TOTAL   (NX * NY)     // 5494
#define KP        64
#define KSTEPS    (KP / 16)     // 4

// ---------------- Tile config ----------------
#define TILE_M    128
#define BT_PER_CTA 4
#define GRID_Y    (B_TOTAL / TILE_M / BT_PER_CTA)   // 16
#define THREADS   384           // 12 warps: 4M x 3N
#define ROWE      72            // W smem row stride in fp16 (144B)

// SMEM layout (bytes): W prologue image overlays DS0 (dead after reg hoist)
#define OFF_W     0
#define W_BYTES   (NU * ROWE * 2)           // 10368
#define DS_STRIDE 68
#define DS_BYTES  (TILE_M * DS_STRIDE * 4)  // 34816
#define OFF_DS0   0
#define OFF_DS1   DS_BYTES                  // 34816
#define OFF_BIAS  (2 * DS_BYTES)            // 69632
#define SMEM_TOTAL (OFF_BIAS + 384)         // 70016 -> 2 CTAs/SM

// ---------------- Scratch (device globals; no allocation allowed) ----------------
// A in mma fragment order: [g32][ks][mf][lane] of uint4, g32 = 32-row group
#define AFRAG_U4  (B_TOTAL * KP * 2 / 16)   // 65536 uint4
__device__ __align__(16) uint4 g_Afrag[AFRAG_U4];
__device__ __align__(16) __half g_Wp[NX * NYP * KP];   // [x][96][64]

static __device__ __forceinline__ uint32_t smem_u32(const void* p) {
    return (uint32_t)__cvta_generic_to_shared(p);
}
static __device__ __forceinline__ void cp_async16(uint32_t dst, const void* src) {
    asm volatile("cp.async.cg.shared.global [%0], [%1], 16;" :: "r"(dst), "l"(src));
}
static __device__ __forceinline__ uint32_t packh2(float a, float b) {
    __half2 h = __floats2half2_rn(a, b);
    return *(uint32_t*)&h;
}

// ---------------- Merged prep kernel (identical layout to round 8) ----------------
#define W_CHUNKS (NX * NYP * 16)                 // 125952
#define PREP_THREADS (AFRAG_U4 + W_CHUNKS)       // 191488
#define PREP_BLOCKS ((PREP_THREADS + 255) / 256) // 749
__global__ void prep_kernel(const float* __restrict__ in, const float* __restrict__ W) {
    int idx = blockIdx.x * 256 + threadIdx.x;
    if (idx < AFRAG_U4) {
        int lane = idx & 31;
        int rest = idx >> 5;
        int mf = rest & 1;
        int ks = (rest >> 1) & 3;
        int g32 = rest >> 3;
        int b0 = g32 * 32 + mf * 16 + (lane >> 2);
        int k0 = ks * 16 + (lane & 3) * 2;
        const float* p = in + b0 * F_DIM + k0;
        float2 v0 = *(const float2*)p;
        float2 v1 = *(const float2*)(p + 8 * F_DIM);
        float2 v2 = *(const float2*)(p + 8);
        float2 v3 = *(const float2*)(p + 8 * F_DIM + 8);
        uint4 o;
        o.x = packh2(v0.x, v0.y);
        o.y = packh2(v1.x, v1.y);
        o.z = packh2(v2.x, v2.y);
        o.w = packh2(v3.x, v3.y);
        g_Afrag[idx] = o;
    } else if (idx < PREP_THREADS) {
        int j = idx - AFRAG_U4;
        int x = j / (NYP * 16);
        int rem = j - x * (NYP * 16);
        int y = rem >> 4;
        int c4 = rem & 15;
        uint2 pack = {0u, 0u};
        if (y < NY) {
            float4 v = *(const float4*)(W + ((size_t)(y * NX + x) * F_DIM + c4 * 4));
            pack.x = packh2(v.x, v.y);
            pack.y = packh2(v.z, v.w);
        }
        *(uint2*)(g_Wp + ((size_t)(x * NYP + y) * KP + c4 * 4)) = pack;
    }
}

// ---------------- GEMM kernel ----------------
// Grid: (x = 0..81, by = 0..15). Block: 384 threads (12 warps, 4M x 3N).
// Warp tile: 32 rows x 24 cols (N padded only to 72). W register-resident.
__global__ __launch_bounds__(THREADS, 2)
void gemm_kernel(const float* __restrict__ bias, float* __restrict__ out) {
    extern __shared__ __align__(16) char smem[];
    float* bias_s = (float*)(smem + OFF_BIAS);   // [96], zero-padded

    const int x  = blockIdx.x;
    const int by = blockIdx.y;
    const int tid = threadIdx.x;
    const int lane = tid & 31;
    const int warp = tid >> 5;
    const int warpM = warp & 3;   // 0..3 (32-row block)
    const int warpN = warp >> 2;  // 0..2 (24-col slice)
    const uint32_t sbase = smem_u32(smem);

    // ---- Prologue: W tile (72 rows) -> smem -> registers ----
    {
        const char* srcW = (const char*)(g_Wp + (size_t)x * NYP * KP);
        #pragma unroll
        for (int i = tid; i < NU * 8; i += THREADS) {
            int r = i >> 3;
            int c = i & 7;
            cp_async16(sbase + OFF_W + r * 144 + c * 16, srcW + r * 128 + c * 16);
        }
        asm volatile("cp.async.commit_group;" ::: "memory");
    }
    if (tid < NYP) bias_s[tid] = (tid < NY) ? bias[tid * NX + x] : 0.0f;
    asm volatile("cp.async.wait_group 0;" ::: "memory");
    __syncthreads();

    // W fragments: 24 cols = 2 frags via x4 + 1 frag via x2. wreg[ks][frag][kh]
    uint32_t wreg[KSTEPS][3][2];
    {
        const uint32_t b4 = sbase + OFF_W
            + ((warpN * 24 + (lane & 15)) * ROWE + (lane >> 4) * 8) * 2;
        const uint32_t b2 = sbase + OFF_W
            + ((warpN * 24 + 16 + (lane & 7)) * ROWE + ((lane >> 3) & 1) * 8) * 2;
        #pragma unroll
        for (int ks = 0; ks < KSTEPS; ks++) {
            uint32_t w0, w1, w2, w3, w4, w5;
            asm volatile("ldmatrix.sync.aligned.m8n8.x4.shared.b16 {%0,%1,%2,%3}, [%4];"
                         : "=r"(w0), "=r"(w1), "=r"(w2), "=r"(w3)
                         : "r"(b4 + ks * 32));
            asm volatile("ldmatrix.sync.aligned.m8n8.x2.shared.b16 {%0,%1}, [%2];"
                         : "=r"(w4), "=r"(w5)
                         : "r"(b2 + ks * 32));
            wreg[ks][0][0] = w0; wreg[ks][0][1] = w2;
            wreg[ks][1][0] = w1; wreg[ks][1][1] = w3;
            wreg[ks][2][0] = w4; wreg[ks][2][1] = w5;
        }
    }
    __syncthreads();   // W smem image dead; DS0 may overwrite

    // d-frag output coordinates
    const int r0 = warpM * 32 + (lane >> 2);
    const int cb = warpN * 24 + (lane & 3) * 2;

    // writeout row range for this warp: warps 0-7 get 11 rows, 8-11 get 10
    const int wr_start = warp * 10 + (warp < 8 ? warp : 8);
    const int wr_count = (warp < 8) ? 11 : 10;

    for (int t = 0; t < BT_PER_CTA; t++) {
        const int bt = by * BT_PER_CTA + t;                  // 128-row tile index
        const uint4* aF = g_Afrag + ((size_t)(bt * 4 + warpM) << 8) + lane;
        float* Ds = (float*)(smem + ((t & 1) ? OFF_DS1 : OFF_DS0));

        float d[2][3][4];
        #pragma unroll
        for (int mf = 0; mf < 2; mf++)
            #pragma unroll
            for (int nf = 0; nf < 3; nf++)
                #pragma unroll
                for (int j = 0; j < 4; j++) d[mf][nf][j] = 0.0f;

        #pragma unroll
        for (int ks = 0; ks < KSTEPS; ks++) {
            uint4 a0 = aF[(ks * 2 + 0) * 32];
            uint4 a1 = aF[(ks * 2 + 1) * 32];
            const uint32_t* am[2] = { (const uint32_t*)&a0, (const uint32_t*)&a1 };
            #pragma unroll
            for (int mf = 0; mf < 2; mf++) {
                #pragma unroll
                for (int nf = 0; nf < 3; nf++) {
                    float* dd = d[mf][nf];
                    asm volatile(
                        "mma.sync.aligned.m16n8k16.row.col.f32.f16.f16.f32 "
                        "{%0,%1,%2,%3}, {%4,%5,%6,%7}, {%8,%9}, {%0,%1,%2,%3};"
                        : "+f"(dd[0]), "+f"(dd[1]), "+f"(dd[2]), "+f"(dd[3])
                        : "r"(am[mf][0]), "r"(am[mf][1]), "r"(am[mf][2]), "r"(am[mf][3]),
                          "r"(wreg[ks][nf][0]), "r"(wreg[ks][nf][1]));
                }
            }
        }

        // ---- Stage to SMEM buffer (bias folded, float2 stores) ----
        #pragma unroll
        for (int nf = 0; nf < 3; nf++) {
            const int y = cb + nf * 8;   // even
            const float b0 = bias_s[y];
            const float b1 = bias_s[y + 1];
            #pragma unroll
            for (int mf = 0; mf < 2; mf++) {
                const int rA = r0 + mf * 16;
                if (y + 1 < NY) {
                    *(float2*)&Ds[rA * DS_STRIDE + y] =
                        make_float2(d[mf][nf][0] + b0, d[mf][nf][1] + b1);
                    *(float2*)&Ds[(rA + 8) * DS_STRIDE + y] =
                        make_float2(d[mf][nf][2] + b0, d[mf][nf][3] + b1);
                } else if (y < NY) {
                    Ds[rA * DS_STRIDE + y]       = d[mf][nf][0] + b0;
                    Ds[(rA + 8) * DS_STRIDE + y] = d[mf][nf][2] + b0;
                }
            }
        }
        __syncthreads();   // ONE sync per tile (double buffer covers reuse)

        // ---- Coalesced writeout: warp = 10-11 rows, lane = col ----
        {
            float* gRow = out + (size_t)(bt * TILE_M + wr_start) * P_TOTAL + x * NY + lane;
            const float* sRow = Ds + wr_start * DS_STRIDE + lane;
            for (int rr = 0; rr < wr_count; rr++) {
                float v0 = sRow[0];
                float v1 = sRow[32];
                gRow[0]  = v0;
                gRow[32] = v1;
                if (lane < 3) gRow[64] = sRow[64];
                sRow += DS_STRIDE;
                gRow += P_TOTAL;
            }
        }
        // no trailing sync: next tile stages into the other buffer
    }
}

// ---------------- Launch ----------------
extern "C" void kernel_launch(void* const* d_in, const int* in_sizes, int n_in,
                              void* d_out, int out_size) {
    const float* inputs = nullptr;  // 8192*64
    const float* W = nullptr;       // 5494*64
    const float* bias = nullptr;    // 5494
    for (int i = 0; i < n_in; i++) {
        if (in_sizes[i] == B_TOTAL * F_DIM) inputs = (const float*)d_in[i];
        else if (in_sizes[i] == P_TOTAL * F_DIM) W = (const float*)d_in[i];
        else if (in_sizes[i] == P_TOTAL) bias = (const float*)d_in[i];
    }
    float* out = (float*)d_out;

    prep_kernel<<<PREP_BLOCKS, 256>>>(inputs, W);

    cudaFuncSetAttribute(gemm_kernel, cudaFuncAttributeMaxDynamicSharedMemorySize, SMEM_TOTAL);
    dim3 grid(NX, GRID_Y);   // (82, 16)
    gemm_kernel<<<grid, THREADS, SMEM_TOTAL>>>(bias, out);
}

// round 11
// speedup vs baseline: 1.0746x; 1.0746x over previous
#include <cuda_runtime.h>
#include <cuda_fp16.h>
#include <cstdint>

// ---------------- Problem constants ----------------
#define B_TOTAL   8192
#define F_DIM     64
#define NX        82
#define NY        67
#define NYP       96
#define P_TOTAL   (NX * NY)      // 5494
#define KP        64             // fp16 K
#define KSTEPS    (KP / 16)      // 4

// ---------------- Tile config (round-7 shape) ----------------
#define TILE_M    128
#define BT_PER_CTA 4
#define GRID_Y    (B_TOTAL / TILE_M / BT_PER_CTA)   // 16
#define ROWE      72             // W smem row stride in fp16 (144B)

// SMEM layout (bytes)
#define A_TILE_BYTES 16384                  // 128x64 fp16 in fragment order
#define OFF_A0    0
#define OFF_A1    A_TILE_BYTES              // 16384
#define OFF_DS    (2 * A_TILE_BYTES)        // 32768
#define DS_STRIDE 68
#define DS_BYTES  (TILE_M * DS_STRIDE * 4)  // 34816
#define OFF_BIAS  (OFF_DS + DS_BYTES)       // 67584
#define OFF_W     OFF_DS                    // W prologue image overlays Ds (dead after hoist)
#define SMEM_TOTAL (OFF_BIAS + 384)         // 67968 -> 2 CTAs/SM

// ---------------- Scratch (device globals; no allocation allowed) ----------------
// A in mma fragment order: [g32][ks][mf][lane] of uint4, g32 = 32-row group
#define AFRAG_U4  (B_TOTAL * KP * 2 / 16)   // 65536 uint4
__device__ __align__(16) uint4 g_Afrag[AFRAG_U4];
__device__ __align__(16) __half g_Wp[NX * NYP * KP];   // [x][96][64]

static __device__ __forceinline__ uint32_t smem_u32(const void* p) {
    return (uint32_t)__cvta_generic_to_shared(p);
}
static __device__ __forceinline__ void cp_async16(uint32_t dst, const void* src) {
    asm volatile("cp.async.cg.shared.global [%0], [%1], 16;" :: "r"(dst), "l"(src));
}
static __device__ __forceinline__ uint32_t packh2(float a, float b) {
    __half2 h = __floats2half2_rn(a, b);
    return *(uint32_t*)&h;
}

// ---------------- Merged prep kernel (layout unchanged) ----------------
#define W_CHUNKS (NX * NYP * 16)                 // 125952
#define PREP_THREADS (AFRAG_U4 + W_CHUNKS)       // 191488
#define PREP_BLOCKS ((PREP_THREADS + 255) / 256) // 749
__global__ void prep_kernel(const float* __restrict__ in, const float* __restrict__ W) {
    int idx = blockIdx.x * 256 + threadIdx.x;
    if (idx < AFRAG_U4) {
        int lane = idx & 31;
        int rest = idx >> 5;
        int mf = rest & 1;
        int ks = (rest >> 1) & 3;
        int g32 = rest >> 3;
        int b0 = g32 * 32 + mf * 16 + (lane >> 2);
        int k0 = ks * 16 + (lane & 3) * 2;
        const float* p = in + b0 * F_DIM + k0;
        float2 v0 = *(const float2*)p;
        float2 v1 = *(const float2*)(p + 8 * F_DIM);
        float2 v2 = *(const float2*)(p + 8);
        float2 v3 = *(const float2*)(p + 8 * F_DIM + 8);
        uint4 o;
        o.x = packh2(v0.x, v0.y);
        o.y = packh2(v1.x, v1.y);
        o.z = packh2(v2.x, v2.y);
        o.w = packh2(v3.x, v3.y);
        g_Afrag[idx] = o;
    } else if (idx < PREP_THREADS) {
        int j = idx - AFRAG_U4;
        int x = j / (NYP * 16);
        int rem = j - x * (NYP * 16);
        int y = rem >> 4;
        int c4 = rem & 15;
        uint2 pack = {0u, 0u};
        if (y < NY) {
            float4 v = *(const float4*)(W + ((size_t)(y * NX + x) * F_DIM + c4 * 4));
            pack.x = packh2(v.x, v.y);
            pack.y = packh2(v.z, v.w);
        }
        *(uint2*)(g_Wp + ((size_t)(x * NYP + y) * KP + c4 * 4)) = pack;
    }
}

// ---------------- GEMM kernel ----------------
// Grid: (x = 0..81, by = 0..15). Block: 256 threads (8 warps, 4M x 2N).
// W register-resident; A pipelined via cp.async double buffer (fragment-order smem).
__global__ __launch_bounds__(256, 2)
void gemm_kernel(const float* __restrict__ bias, float* __restrict__ out) {
    extern __shared__ __align__(16) char smem[];
    float* Ds = (float*)(smem + OFF_DS);         // [128][68] staging
    float* bias_s = (float*)(smem + OFF_BIAS);   // [96], zero-padded

    const int x  = blockIdx.x;
    const int by = blockIdx.y;
    const int tid = threadIdx.x;
    const int lane = tid & 31;
    const int warp = tid >> 5;
    const int warpM = warp & 3;   // 0..3
    const int warpN = warp >> 2;  // 0..1
    const uint32_t sbase = smem_u32(smem);

    // ---- Prologue: W tile + A[0] via one cp.async group ----
    {
        const char* srcW = (const char*)(g_Wp + (size_t)x * NYP * KP);
        #pragma unroll
        for (int i = tid; i < NYP * 8; i += 256) {
            int r = i >> 3;
            int c = i & 7;
            cp_async16(sbase + OFF_W + r * 144 + c * 16, srcW + r * 128 + c * 16);
        }
        const char* srcA = (const char*)(g_Afrag + ((size_t)(by * BT_PER_CTA * 4) << 8));
        #pragma unroll
        for (int i = tid; i < A_TILE_BYTES / 16; i += 256)   // 1024 chunks
            cp_async16(sbase + OFF_A0 + i * 16, srcA + i * 16);
        asm volatile("cp.async.commit_group;" ::: "memory");
    }
    if (tid < NYP) bias_s[tid] = (tid < NY) ? bias[tid * NX + x] : 0.0f;
    asm volatile("cp.async.wait_group 0;" ::: "memory");
    __syncthreads();

    // ---- Hoist W fragments to registers (once) ----
    uint32_t wreg[KSTEPS][3][4];
    {
        const uint32_t b_base = sbase + OFF_W
            + ((warpN * 48 + (lane & 15)) * ROWE + (lane >> 4) * 8) * 2;
        const uint32_t NG_STRIDE = 16 * ROWE * 2;
        #pragma unroll
        for (int ks = 0; ks < KSTEPS; ks++) {
            #pragma unroll
            for (int g = 0; g < 3; g++) {
                asm volatile("ldmatrix.sync.aligned.m8n8.x4.shared.b16 {%0,%1,%2,%3}, [%4];"
                             : "=r"(wreg[ks][g][0]), "=r"(wreg[ks][g][1]),
                               "=r"(wreg[ks][g][2]), "=r"(wreg[ks][g][3])
                             : "r"(b_base + g * NG_STRIDE + ks * 32));
            }
        }
    }
    __syncthreads();   // W smem image dead; Ds may overwrite

    // d-frag output coordinates
    const int r0 = warpM * 32 + (lane >> 2);
    const int cb = warpN * 48 + (lane & 3) * 2;

    // per-thread A-fragment smem base: warpM group of 4KB, lane slot of 16B
    const uint32_t aOffBase = (uint32_t)(warpM * 4096 + lane * 16);

    for (int t = 0; t < BT_PER_CTA; t++) {
        const int bt = by * BT_PER_CTA + t;
        const uint32_t aBuf = sbase + ((t & 1) ? OFF_A1 : OFF_A0) + aOffBase;

        // ---- Prefetch A[t+1] into the other buffer (hidden under compute+epilogue) ----
        if (t + 1 < BT_PER_CTA) {
            const char* srcA = (const char*)(g_Afrag + ((size_t)((bt + 1) * 4) << 8));
            const uint32_t dst = sbase + ((t & 1) ? OFF_A0 : OFF_A1);
            #pragma unroll
            for (int i = tid; i < A_TILE_BYTES / 16; i += 256)
                cp_async16(dst + i * 16, srcA + i * 16);
            asm volatile("cp.async.commit_group;" ::: "memory");
        }

        float d[2][6][4];
        #pragma unroll
        for (int mf = 0; mf < 2; mf++)
            #pragma unroll
            for (int nf = 0; nf < 6; nf++)
                #pragma unroll
                for (int j = 0; j < 4; j++) d[mf][nf][j] = 0.0f;

        #pragma unroll
        for (int ks = 0; ks < KSTEPS; ks++) {
            // A fragments from smem (fragment-order): one LDS.128 each, conflict-free
            uint4 a0, a1;
            asm volatile("ld.shared.v4.b32 {%0,%1,%2,%3}, [%4];"
                         : "=r"(a0.x), "=r"(a0.y), "=r"(a0.z), "=r"(a0.w)
                         : "r"(aBuf + (ks * 2 + 0) * 512));
            asm volatile("ld.shared.v4.b32 {%0,%1,%2,%3}, [%4];"
                         : "=r"(a1.x), "=r"(a1.y), "=r"(a1.z), "=r"(a1.w)
                         : "r"(aBuf + (ks * 2 + 1) * 512));
            const uint32_t* am[2] = { (const uint32_t*)&a0, (const uint32_t*)&a1 };
            #pragma unroll
            for (int mf = 0; mf < 2; mf++) {
                #pragma unroll
                for (int g = 0; g < 3; g++) {
                    #pragma unroll
                    for (int h = 0; h < 2; h++) {
                        float* dd = d[mf][g * 2 + h];
                        asm volatile(
                            "mma.sync.aligned.m16n8k16.row.col.f32.f16.f16.f32 "
                            "{%0,%1,%2,%3}, {%4,%5,%6,%7}, {%8,%9}, {%0,%1,%2,%3};"
                            : "+f"(dd[0]), "+f"(dd[1]), "+f"(dd[2]), "+f"(dd[3])
                            : "r"(am[mf][0]), "r"(am[mf][1]), "r"(am[mf][2]), "r"(am[mf][3]),
                              "r"(wreg[ks][g][h]), "r"(wreg[ks][g][2 + h]));
                    }
                }
            }
        }

        // ---- Stage to SMEM with bias folded (float2 stores) ----
        // (Ds free: prologue sync on t=0, end-of-tile sync otherwise)
        #pragma unroll
        for (int nf = 0; nf < 6; nf++) {
            const int y = cb + nf * 8;   // even
            const float b0 = bias_s[y];
            const float b1 = bias_s[y + 1];
            #pragma unroll
            for (int mf = 0; mf < 2; mf++) {
                const int rA = r0 + mf * 16;
                if (y + 1 < NY) {
                    *(float2*)&Ds[rA * DS_STRIDE + y] =
                        make_float2(d[mf][nf][0] + b0, d[mf][nf][1] + b1);
                    *(float2*)&Ds[(rA + 8) * DS_STRIDE + y] =
                        make_float2(d[mf][nf][2] + b0, d[mf][nf][3] + b1);
                } else if (y < NY) {
                    Ds[rA * DS_STRIDE + y]       = d[mf][nf][0] + b0;
                    Ds[(rA + 8) * DS_STRIDE + y] = d[mf][nf][2] + b0;
                }
            }
        }
        __syncthreads();

        // ---- Coalesced writeout: warp = 16 rows, lane = col ----
        {
            float* gRow = out + (size_t)(bt * TILE_M + warp * 16) * P_TOTAL + x * NY + lane;
            const float* sRow = Ds + (warp * 16) * DS_STRIDE + lane;
            #pragma unroll
            for (int rr = 0; rr < 16; rr++) {
                float v0 = sRow[0];
                float v1 = sRow[32];
                gRow[0]  = v0;
                gRow[32] = v1;
                if (lane < 3) gRow[64] = sRow[64];
                sRow += DS_STRIDE;
                gRow += P_TOTAL;
            }
        }

        // ---- Close the pipeline stage: A[t+1] landed, Ds free ----
        asm volatile("cp.async.wait_group 0;" ::: "memory");
        __syncthreads();
    }
}

// ---------------- Launch ----------------
extern "C" void kernel_launch(void* const* d_in, const int* in_sizes, int n_in,
                              void* d_out, int out_size) {
    const float* inputs = nullptr;  // 8192*64
    const float* W = nullptr;       // 5494*64
    const float* bias = nullptr;    // 5494
    for (int i = 0; i < n_in; i++) {
        if (in_sizes[i] == B_TOTAL * F_DIM) inputs = (const float*)d_in[i];
        else if (in_sizes[i] == P_TOTAL * F_DIM) W = (const float*)d_in[i];
        else if (in_sizes[i] == P_TOTAL) bias = (const float*)d_in[i];
    }
    float* out = (float*)d_out;

    prep_kernel<<<PREP_BLOCKS, 256>>>(inputs, W);

    cudaFuncSetAttribute(gemm_kernel, cudaFuncAttributeMaxDynamicSharedMemorySize, SMEM_TOTAL);
    dim3 grid(NX, GRID_Y);   // (82, 16)
    gemm_kernel<<<grid, 256, SMEM_TOTAL>>>(bias, out);
}

// round 12
// speedup vs baseline: 1.1153x; 1.0379x over previous
#include <cuda_runtime.h>
#include <cuda_fp16.h>
#include <cstdint>

// ---------------- Problem constants ----------------
#define B_TOTAL   8192
#define F_DIM     64
#define NX        82
#define NY        67
#define NYP       96
#define P_TOTAL   (NX * NY)      // 5494
#define KP        64             // fp16 K
#define KSTEPS    (KP / 16)      // 4

// ---------------- Tile config (round-7/11 shape) ----------------
#define TILE_M    128
#define BT_PER_CTA 4
#define GRID_Y    (B_TOTAL / TILE_M / BT_PER_CTA)   // 16
#define ROWE      72             // W smem row stride in fp16 (144B)

// SMEM layout (bytes)
#define A_TILE_BYTES 16384                  // 128x64 fp16 in fragment order
#define OFF_A0    0
#define OFF_A1    A_TILE_BYTES              // 16384
#define OFF_DS    (2 * A_TILE_BYTES)        // 32768
#define DS_STRIDE 68
#define DS_BYTES  (TILE_M * DS_STRIDE * 4)  // 34816
#define OFF_BIAS  (OFF_DS + DS_BYTES)       // 67584
#define OFF_W     OFF_DS                    // W prologue image overlays Ds (dead after hoist)
#define SMEM_TOTAL (OFF_BIAS + 384)         // 67968 -> 2 CTAs/SM

// ---------------- Scratch (device globals; no allocation allowed) ----------------
// A in mma fragment order: [g32][ks][mf][lane] of uint4, g32 = 32-row group
#define AFRAG_U4  (B_TOTAL * KP * 2 / 16)   // 65536 uint4
__device__ __align__(16) uint4 g_Afrag[AFRAG_U4];
__device__ __align__(16) __half g_Wp[NX * NYP * KP];   // [x][96][64]

static __device__ __forceinline__ uint32_t smem_u32(const void* p) {
    return (uint32_t)__cvta_generic_to_shared(p);
}
static __device__ __forceinline__ void cp_async16(uint32_t dst, const void* src) {
    asm volatile("cp.async.cg.shared.global [%0], [%1], 16;" :: "r"(dst), "l"(src));
}
static __device__ __forceinline__ uint32_t packh2(float a, float b) {
    __half2 h = __floats2half2_rn(a, b);
    return *(uint32_t*)&h;
}

// ---------------- Merged prep kernel (layout unchanged) ----------------
#define W_CHUNKS (NX * NYP * 16)                 // 125952
#define PREP_THREADS (AFRAG_U4 + W_CHUNKS)       // 191488
#define PREP_BLOCKS ((PREP_THREADS + 255) / 256) // 749
__global__ void prep_kernel(const float* __restrict__ in, const float* __restrict__ W) {
    int idx = blockIdx.x * 256 + threadIdx.x;
    if (idx < AFRAG_U4) {
        int lane = idx & 31;
        int rest = idx >> 5;
        int mf = rest & 1;
        int ks = (rest >> 1) & 3;
        int g32 = rest >> 3;
        int b0 = g32 * 32 + mf * 16 + (lane >> 2);
        int k0 = ks * 16 + (lane & 3) * 2;
        const float* p = in + b0 * F_DIM + k0;
        float2 v0 = *(const float2*)p;
        float2 v1 = *(const float2*)(p + 8 * F_DIM);
        float2 v2 = *(const float2*)(p + 8);
        float2 v3 = *(const float2*)(p + 8 * F_DIM + 8);
        uint4 o;
        o.x = packh2(v0.x, v0.y);
        o.y = packh2(v1.x, v1.y);
        o.z = packh2(v2.x, v2.y);
        o.w = packh2(v3.x, v3.y);
        g_Afrag[idx] = o;
    } else if (idx < PREP_THREADS) {
        int j = idx - AFRAG_U4;
        int x = j / (NYP * 16);
        int rem = j - x * (NYP * 16);
        int y = rem >> 4;
        int c4 = rem & 15;
        uint2 pack = {0u, 0u};
        if (y < NY) {
            float4 v = *(const float4*)(W + ((size_t)(y * NX + x) * F_DIM + c4 * 4));
            pack.x = packh2(v.x, v.y);
            pack.y = packh2(v.z, v.w);
        }
        *(uint2*)(g_Wp + ((size_t)(x * NYP + y) * KP + c4 * 4)) = pack;
    }
}

// ---------------- GEMM kernel ----------------
// Grid: (x = 0..81, by = 0..15). Block: 256 threads (8 warps, 4M x 2N).
// W register-resident; A cp.async double buffer; tile t's MMA overlapped with
// tile t-1's writeout (chunk-interleaved into the k-loop).
__global__ __launch_bounds__(256, 2)
void gemm_kernel(const float* __restrict__ bias, float* __restrict__ out) {
    extern __shared__ __align__(16) char smem[];
    float* Ds = (float*)(smem + OFF_DS);         // [128][68] staging
    float* bias_s = (float*)(smem + OFF_BIAS);   // [96], zero-padded

    const int x  = blockIdx.x;
    const int by = blockIdx.y;
    const int tid = threadIdx.x;
    const int lane = tid & 31;
    const int warp = tid >> 5;
    const int warpM = warp & 3;   // 0..3
    const int warpN = warp >> 2;  // 0..1
    const uint32_t sbase = smem_u32(smem);

    // ---- Prologue: W tile + A[0] via one cp.async group ----
    {
        const char* srcW = (const char*)(g_Wp + (size_t)x * NYP * KP);
        #pragma unroll
        for (int i = tid; i < NYP * 8; i += 256) {
            int r = i >> 3;
            int c = i & 7;
            cp_async16(sbase + OFF_W + r * 144 + c * 16, srcW + r * 128 + c * 16);
        }
        const char* srcA = (const char*)(g_Afrag + ((size_t)(by * BT_PER_CTA * 4) << 8));
        #pragma unroll
        for (int i = tid; i < A_TILE_BYTES / 16; i += 256)   // 1024 chunks
            cp_async16(sbase + OFF_A0 + i * 16, srcA + i * 16);
        asm volatile("cp.async.commit_group;" ::: "memory");
    }
    if (tid < NYP) bias_s[tid] = (tid < NY) ? bias[tid * NX + x] : 0.0f;
    asm volatile("cp.async.wait_group 0;" ::: "memory");
    __syncthreads();

    // ---- Hoist W fragments to registers (once) ----
    uint32_t wreg[KSTEPS][3][4];
    {
        const uint32_t b_base = sbase + OFF_W
            + ((warpN * 48 + (lane & 15)) * ROWE + (lane >> 4) * 8) * 2;
        const uint32_t NG_STRIDE = 16 * ROWE * 2;
        #pragma unroll
        for (int ks = 0; ks < KSTEPS; ks++) {
            #pragma unroll
            for (int g = 0; g < 3; g++) {
                asm volatile("ldmatrix.sync.aligned.m8n8.x4.shared.b16 {%0,%1,%2,%3}, [%4];"
                             : "=r"(wreg[ks][g][0]), "=r"(wreg[ks][g][1]),
                               "=r"(wreg[ks][g][2]), "=r"(wreg[ks][g][3])
                             : "r"(b_base + g * NG_STRIDE + ks * 32));
            }
        }
    }
    __syncthreads();   // W smem image dead; Ds may be overwritten from here on

    // d-frag output coordinates
    const int r0 = warpM * 32 + (lane >> 2);
    const int cb = warpN * 48 + (lane & 3) * 2;

    // per-thread A-fragment smem base: warpM group of 4KB, lane slot of 16B
    const uint32_t aOffBase = (uint32_t)(warpM * 4096 + lane * 16);

    #pragma unroll
    for (int t = 0; t < BT_PER_CTA; t++) {
        const int bt = by * BT_PER_CTA + t;
        const uint32_t aBuf = sbase + ((t & 1) ? OFF_A1 : OFF_A0) + aOffBase;

        // ---- Prefetch A[t+1] (buffer free: all warps passed compute(t-1) + 2 bars) ----
        if (t + 1 < BT_PER_CTA) {
            const char* srcA = (const char*)(g_Afrag + ((size_t)((bt + 1) * 4) << 8));
            const uint32_t dst = sbase + ((t & 1) ? OFF_A0 : OFF_A1);
            #pragma unroll
            for (int i = tid; i < A_TILE_BYTES / 16; i += 256)
                cp_async16(dst + i * 16, srcA + i * 16);
            asm volatile("cp.async.commit_group;" ::: "memory");
        }

        float d[2][6][4];
        #pragma unroll
        for (int mf = 0; mf < 2; mf++)
            #pragma unroll
            for (int nf = 0; nf < 6; nf++)
                #pragma unroll
                for (int j = 0; j < 4; j++) d[mf][nf][j] = 0.0f;

        // previous tile's writeout walkers (valid when t > 0)
        float* gRowW = out + ((size_t)((bt - 1) * TILE_M + warp * 16)) * P_TOTAL + x * NY + lane;
        const float* sRowW = Ds + (warp * 16) * DS_STRIDE + lane;

        // ---- Merged window: compute d(t) interleaved with writeout(t-1) ----
        #pragma unroll
        for (int ks = 0; ks < KSTEPS; ks++) {
            uint4 a0, a1;
            asm volatile("ld.shared.v4.b32 {%0,%1,%2,%3}, [%4];"
                         : "=r"(a0.x), "=r"(a0.y), "=r"(a0.z), "=r"(a0.w)
                         : "r"(aBuf + (ks * 2 + 0) * 512));
            asm volatile("ld.shared.v4.b32 {%0,%1,%2,%3}, [%4];"
                         : "=r"(a1.x), "=r"(a1.y), "=r"(a1.z), "=r"(a1.w)
                         : "r"(aBuf + (ks * 2 + 1) * 512));
            const uint32_t* am[2] = { (const uint32_t*)&a0, (const uint32_t*)&a1 };
            #pragma unroll
            for (int mf = 0; mf < 2; mf++) {
                #pragma unroll
                for (int g = 0; g < 3; g++) {
                    #pragma unroll
                    for (int h = 0; h < 2; h++) {
                        float* dd = d[mf][g * 2 + h];
                        asm volatile(
                            "mma.sync.aligned.m16n8k16.row.col.f32.f16.f16.f32 "
                            "{%0,%1,%2,%3}, {%4,%5,%6,%7}, {%8,%9}, {%0,%1,%2,%3};"
                            : "+f"(dd[0]), "+f"(dd[1]), "+f"(dd[2]), "+f"(dd[3])
                            : "r"(am[mf][0]), "r"(am[mf][1]), "r"(am[mf][2]), "r"(am[mf][3]),
                              "r"(wreg[ks][g][h]), "r"(wreg[ks][g][2 + h]));
                    }
                }
            }
            // writeout chunk of previous tile: 4 rows per K-step
            if (t > 0) {
                #pragma unroll
                for (int rr = 0; rr < 4; rr++) {
                    float v0 = sRowW[0];
                    float v1 = sRowW[32];
                    gRowW[0]  = v0;
                    gRowW[32] = v1;
                    if (lane < 3) gRowW[64] = sRowW[64];
                    sRowW += DS_STRIDE;
                    gRowW += P_TOTAL;
                }
            }
        }
        __syncthreads();   // all Ds reads (writeout t-1) done; compute(t) done

        // ---- Stage d(t) to SMEM with bias folded (float2 stores) ----
        #pragma unroll
        for (int nf = 0; nf < 6; nf++) {
            const int y = cb + nf * 8;   // even
            const float b0 = bias_s[y];
            const float b1 = bias_s[y + 1];
            #pragma unroll
            for (int mf = 0; mf < 2; mf++) {
                const int rA = r0 + mf * 16;
                if (y + 1 < NY) {
                    *(float2*)&Ds[rA * DS_STRIDE + y] =
                        make_float2(d[mf][nf][0] + b0, d[mf][nf][1] + b1);
                    *(float2*)&Ds[(rA + 8) * DS_STRIDE + y] =
                        make_float2(d[mf][nf][2] + b0, d[mf][nf][3] + b1);
                } else if (y < NY) {
                    Ds[rA * DS_STRIDE + y]       = d[mf][nf][0] + b0;
                    Ds[(rA + 8) * DS_STRIDE + y] = d[mf][nf][2] + b0;
                }
            }
        }
        asm volatile("cp.async.wait_group 0;" ::: "memory");   // A[t+1] landed (this thread)
        __syncthreads();   // Ds(t) ready; A[t+1] visible to all
    }

    // ---- Final writeout: last tile ----
    {
        const int btL = by * BT_PER_CTA + BT_PER_CTA - 1;
        float* gRow = out + (size_t)(btL * TILE_M + warp * 16) * P_TOTAL + x * NY + lane;
        const float* sRow = Ds + (warp * 16) * DS_STRIDE + lane;
        #pragma unroll
        for (int rr = 0; rr < 16; rr++) {
            float v0 = sRow[0];
            float v1 = sRow[32];
            gRow[0]  = v0;
            gRow[32] = v1;
            if (lane < 3) gRow[64] = sRow[64];
            sRow += DS_STRIDE;
            gRow += P_TOTAL;
        }
    }
}

// ---------------- Launch ----------------
extern "C" void kernel_launch(void* const* d_in, const int* in_sizes, int n_in,
                              void* d_out, int out_size) {
    const float* inputs = nullptr;  // 8192*64
    const float* W = nullptr;       // 5494*64
    const float* bias = nullptr;    // 5494
    for (int i = 0; i < n_in; i++) {
        if (in_sizes[i] == B_TOTAL * F_DIM) inputs = (const float*)d_in[i];
        else if (in_sizes[i] == P_TOTAL * F_DIM) W = (const float*)d_in[i];
        else if (in_sizes[i] == P_TOTAL) bias = (const float*)d_in[i];
    }
    float* out = (float*)d_out;

    prep_kernel<<<PREP_BLOCKS, 256>>>(inputs, W);

    cudaFuncSetAttribute(gemm_kernel, cudaFuncAttributeMaxDynamicSharedMemorySize, SMEM_TOTAL);
    dim3 grid(NX, GRID_Y);   // (82, 16)
    gemm_kernel<<<grid, 256, SMEM_TOTAL>>>(bias, out);
}